// round 1
// baseline (speedup 1.0000x reference)
#include <cuda_runtime.h>

#define BATCH 4
#define HEADS 8
#define SEQ   2048
#define HDIM  64
#define EMB   512
#define BH    (BATCH*HEADS)
#define MTOT  (BATCH*SEQ)

#define NEG_INF __int_as_float(0xff800000)

// Scratch (allocation-free rule: __device__ globals). 4 x 16MB = 64MB.
static __device__ float g_q[BH*SEQ*HDIM];
static __device__ float g_k[BH*SEQ*HDIM];
static __device__ float g_v[BH*SEQ*HDIM];
static __device__ float g_o[BATCH*SEQ*EMB];

// ---------------------------------------------------------------------------
// GEMM: C[M=8192, N] = X[8192,512] @ W[512,N=512-slice] + bias
// BM=128, BN=64, BK=16, 256 threads, 8x4 micro-tile, fp32.
// permute=1: write to per-head layout [b,h,l,d]; permute=0: row-major [m,n].
// ---------------------------------------------------------------------------
__global__ __launch_bounds__(256) void proj_kernel(
    const float* __restrict__ X, const float* __restrict__ W,
    const float* __restrict__ bias, float* __restrict__ Out, int permute)
{
    __shared__ float As[16][132];   // [k][m], padded
    __shared__ float Bs[16][68];    // [k][n], padded
    const int t  = threadIdx.x;
    const int tx = t & 15, ty = t >> 4;
    const int m0 = blockIdx.y * 128;
    const int n0 = blockIdx.x * 64;

    float acc[8][4];
    #pragma unroll
    for (int i = 0; i < 8; i++)
        #pragma unroll
        for (int j = 0; j < 4; j++) acc[i][j] = 0.f;

    for (int k0 = 0; k0 < EMB; k0 += 16) {
        #pragma unroll
        for (int s = 0; s < 2; s++) {
            int idx = t + s * 256;          // 0..511
            int row = idx >> 2;             // 0..127
            int k4  = (idx & 3) << 2;       // 0,4,8,12
            float4 v = *(const float4*)(X + (size_t)(m0 + row) * EMB + k0 + k4);
            As[k4 + 0][row] = v.x; As[k4 + 1][row] = v.y;
            As[k4 + 2][row] = v.z; As[k4 + 3][row] = v.w;
        }
        {
            int row = t >> 4;               // 0..15
            int n4  = (t & 15) << 2;        // 0..60
            *(float4*)&Bs[row][n4] =
                *(const float4*)(W + (size_t)(k0 + row) * EMB + n0 + n4);
        }
        __syncthreads();
        #pragma unroll
        for (int kk = 0; kk < 16; kk++) {
            float a[8], b[4];
            *(float4*)(a)     = *(float4*)&As[kk][ty * 8];
            *(float4*)(a + 4) = *(float4*)&As[kk][ty * 8 + 4];
            *(float4*)(b)     = *(float4*)&Bs[kk][tx * 4];
            #pragma unroll
            for (int i = 0; i < 8; i++)
                #pragma unroll
                for (int j = 0; j < 4; j++)
                    acc[i][j] = fmaf(a[i], b[j], acc[i][j]);
        }
        __syncthreads();
    }

    #pragma unroll
    for (int i = 0; i < 8; i++) {
        int m = m0 + ty * 8 + i;
        #pragma unroll
        for (int j = 0; j < 4; j++) {
            int n = n0 + tx * 4 + j;
            float v = acc[i][j] + bias[n];
            if (permute) {
                int b_ = m >> 11, l = m & 2047;   // m = b*2048 + l
                int h  = n >> 6,  d = n & 63;     // n = h*64 + d
                g_q[0]; // no-op to keep compiler honest about globals
                Out[(((size_t)(b_ * HEADS + h) * SEQ + l) << 6) + d] = v;
            } else {
                Out[(size_t)m * EMB + n] = v;
            }
        }
    }
}

// ---------------------------------------------------------------------------
// Scores: S[z][q][k] = (q . k)/8 + grm[q][k], masked -> -inf.
// Per z = b*8+h. BM=128 (q), BN=64 (k), K=HDIM=64, BK=16.
// Writes raw masked scores into the attention-weights region of d_out.
// ---------------------------------------------------------------------------
__global__ __launch_bounds__(256) void scores_kernel(
    const int* __restrict__ mask, const float* __restrict__ grm,
    float* __restrict__ attn)
{
    __shared__ float Qs[16][132];
    __shared__ float Ks[16][68];
    const int t  = threadIdx.x;
    const int tx = t & 15, ty = t >> 4;
    const int z  = blockIdx.z;
    const int m0 = blockIdx.y * 128;
    const int n0 = blockIdx.x * 64;
    const float* Q  = g_q + (size_t)z * SEQ * HDIM;
    const float* Kp = g_k + (size_t)z * SEQ * HDIM;

    float acc[8][4];
    #pragma unroll
    for (int i = 0; i < 8; i++)
        #pragma unroll
        for (int j = 0; j < 4; j++) acc[i][j] = 0.f;

    for (int k0 = 0; k0 < HDIM; k0 += 16) {
        #pragma unroll
        for (int s = 0; s < 2; s++) {
            int idx = t + s * 256;
            int row = idx >> 2;
            int k4  = (idx & 3) << 2;
            float4 v = *(const float4*)(Q + (size_t)(m0 + row) * HDIM + k0 + k4);
            Qs[k4 + 0][row] = v.x; Qs[k4 + 1][row] = v.y;
            Qs[k4 + 2][row] = v.z; Qs[k4 + 3][row] = v.w;
        }
        {
            int kl = t >> 2;                // 0..63 (k column)
            int d4 = (t & 3) << 2;          // 0,4,8,12
            float4 v = *(const float4*)(Kp + (size_t)(n0 + kl) * HDIM + k0 + d4);
            Ks[d4 + 0][kl] = v.x; Ks[d4 + 1][kl] = v.y;
            Ks[d4 + 2][kl] = v.z; Ks[d4 + 3][kl] = v.w;
        }
        __syncthreads();
        #pragma unroll
        for (int kk = 0; kk < 16; kk++) {
            float a[8], b[4];
            *(float4*)(a)     = *(float4*)&Qs[kk][ty * 8];
            *(float4*)(a + 4) = *(float4*)&Qs[kk][ty * 8 + 4];
            *(float4*)(b)     = *(float4*)&Ks[kk][tx * 4];
            #pragma unroll
            for (int i = 0; i < 8; i++)
                #pragma unroll
                for (int j = 0; j < 4; j++)
                    acc[i][j] = fmaf(a[i], b[j], acc[i][j]);
        }
        __syncthreads();
    }

    const float scale = 0.125f;            // 1/sqrt(64)
    const int b_ = z >> 3;
    float* out = attn + (size_t)z * SEQ * SEQ;
    #pragma unroll
    for (int i = 0; i < 8; i++) {
        int q = m0 + ty * 8 + i;
        #pragma unroll
        for (int j = 0; j < 4; j++) {
            int kc = n0 + tx * 4 + j;
            float s = acc[i][j] * scale + grm[(size_t)q * SEQ + kc];
            int mv  = mask[((size_t)b_ * SEQ + q) * SEQ + kc];
            out[(size_t)q * SEQ + kc] = mv ? s : NEG_INF;
        }
    }
}

// ---------------------------------------------------------------------------
// Row softmax in place, one block per (z,q) row of 2048.
// ---------------------------------------------------------------------------
__device__ __forceinline__ float warpMaxf(float v) {
    #pragma unroll
    for (int o = 16; o; o >>= 1) v = fmaxf(v, __shfl_xor_sync(0xffffffffu, v, o));
    return v;
}
__device__ __forceinline__ float warpSumf(float v) {
    #pragma unroll
    for (int o = 16; o; o >>= 1) v += __shfl_xor_sync(0xffffffffu, v, o);
    return v;
}

__global__ __launch_bounds__(256) void softmax_kernel(float* __restrict__ attn)
{
    __shared__ float red[8];
    __shared__ float bc;
    const int t = threadIdx.x;
    const int lane = t & 31, w = t >> 5;
    float* p = attn + (size_t)blockIdx.x * SEQ;

    float x[8];
    #pragma unroll
    for (int i = 0; i < 8; i++) x[i] = p[t + i * 256];

    float m = x[0];
    #pragma unroll
    for (int i = 1; i < 8; i++) m = fmaxf(m, x[i]);
    m = warpMaxf(m);
    if (lane == 0) red[w] = m;
    __syncthreads();
    if (w == 0) {
        float v = (lane < 8) ? red[lane] : NEG_INF;
        v = warpMaxf(v);
        if (lane == 0) bc = v;
    }
    __syncthreads();
    m = bc;

    float e[8], s = 0.f;
    #pragma unroll
    for (int i = 0; i < 8; i++) { e[i] = expf(x[i] - m); s += e[i]; }
    s = warpSumf(s);
    if (lane == 0) red[w] = s;
    __syncthreads();
    if (w == 0) {
        float v = (lane < 8) ? red[lane] : 0.f;
        v = warpSumf(v);
        if (lane == 0) bc = v;
    }
    __syncthreads();
    const float inv = 1.0f / bc;
    #pragma unroll
    for (int i = 0; i < 8; i++) p[t + i * 256] = e[i] * inv;
}

// ---------------------------------------------------------------------------
// O[z][q][d] = sum_k P[z][q][k] * V[z][k][d].  BM=64, BN=64(=HDIM), BK=32.
// Writes to g_o in [B, L, E] layout (h*64+d column) for the final projection.
// ---------------------------------------------------------------------------
__global__ __launch_bounds__(256) void av_kernel(const float* __restrict__ attn)
{
    __shared__ float As[32][68];   // [k][q]
    __shared__ float Bs[32][68];   // [k][d]
    const int t  = threadIdx.x;
    const int tx = t & 15, ty = t >> 4;
    const int z  = blockIdx.z;
    const int m0 = blockIdx.y * 64;
    const float* P = attn + (size_t)z * SEQ * SEQ;
    const float* V = g_v + (size_t)z * SEQ * HDIM;

    float acc[4][4];
    #pragma unroll
    for (int i = 0; i < 4; i++)
        #pragma unroll
        for (int j = 0; j < 4; j++) acc[i][j] = 0.f;

    for (int k0 = 0; k0 < SEQ; k0 += 32) {
        #pragma unroll
        for (int s = 0; s < 2; s++) {
            int idx = t + s * 256;          // 0..511
            int row = idx >> 3;             // 0..63
            int k4  = (idx & 7) << 2;       // 0..28
            float4 v = *(const float4*)(P + (size_t)(m0 + row) * SEQ + k0 + k4);
            As[k4 + 0][row] = v.x; As[k4 + 1][row] = v.y;
            As[k4 + 2][row] = v.z; As[k4 + 3][row] = v.w;
        }
        #pragma unroll
        for (int s = 0; s < 2; s++) {
            int idx = t + s * 256;
            int row = idx >> 4;             // 0..31
            int n4  = (idx & 15) << 2;      // 0..60
            *(float4*)&Bs[row][n4] =
                *(const float4*)(V + (size_t)(k0 + row) * HDIM + n4);
        }
        __syncthreads();
        #pragma unroll
        for (int kk = 0; kk < 32; kk++) {
            float a[4], b[4];
            *(float4*)a = *(float4*)&As[kk][ty * 4];
            *(float4*)b = *(float4*)&Bs[kk][tx * 4];
            #pragma unroll
            for (int i = 0; i < 4; i++)
                #pragma unroll
                for (int j = 0; j < 4; j++)
                    acc[i][j] = fmaf(a[i], b[j], acc[i][j]);
        }
        __syncthreads();
    }

    const int b_ = z >> 3, h = z & 7;
    #pragma unroll
    for (int i = 0; i < 4; i++) {
        int l = m0 + ty * 4 + i;
        #pragma unroll
        for (int j = 0; j < 4; j++) {
            g_o[((size_t)b_ * SEQ + l) * EMB + h * HDIM + tx * 4 + j] = acc[i][j];
        }
    }
}

// ---------------------------------------------------------------------------
extern "C" void kernel_launch(void* const* d_in, const int* in_sizes, int n_in,
                              void* d_out, int out_size)
{
    const float* query = (const float*)d_in[0];
    const float* key_  = (const float*)d_in[1];
    const float* value = (const float*)d_in[2];
    const int*   mask  = (const int*)  d_in[3];
    const float* grm   = (const float*)d_in[4];
    const float* Wq = (const float*)d_in[5];
    const float* bq = (const float*)d_in[6];
    const float* Wk = (const float*)d_in[7];
    const float* bk = (const float*)d_in[8];
    const float* Wv = (const float*)d_in[9];
    const float* bv = (const float*)d_in[10];
    const float* Wo = (const float*)d_in[11];
    const float* bo = (const float*)d_in[12];

    float* out  = (float*)d_out;                         // [B, L, E]
    float* attn = out + (size_t)BATCH * SEQ * EMB;       // [B, H, L, L]

    float *q_, *k_, *v_, *o_;
    cudaGetSymbolAddress((void**)&q_, g_q);
    cudaGetSymbolAddress((void**)&k_, g_k);
    cudaGetSymbolAddress((void**)&v_, g_v);
    cudaGetSymbolAddress((void**)&o_, g_o);

    dim3 gProj(EMB / 64, MTOT / 128);        // (8, 64)
    proj_kernel<<<gProj, 256>>>(query, Wq, bq, q_, 1);
    proj_kernel<<<gProj, 256>>>(key_,  Wk, bk, k_, 1);
    proj_kernel<<<gProj, 256>>>(value, Wv, bv, v_, 1);

    dim3 gSc(SEQ / 64, SEQ / 128, BH);       // (32, 16, 32)
    scores_kernel<<<gSc, 256>>>(mask, grm, attn);

    softmax_kernel<<<BH * SEQ, 256>>>(attn); // 65536 rows

    dim3 gAv(1, SEQ / 64, BH);               // (1, 32, 32)
    av_kernel<<<gAv, 256>>>(attn);

    proj_kernel<<<gProj, 256>>>(o_, Wo, bo, out, 0);
}

// round 2
// speedup vs baseline: 1.3093x; 1.3093x over previous
#include <cuda_runtime.h>
#include <cstdint>

#define BATCH 4
#define HEADS 8
#define SEQ   2048
#define HDIM  64
#define EMB   512
#define BH    (BATCH*HEADS)
#define MTOT  (BATCH*SEQ)
#define BIG_NEG (-1e30f)

// Scratch (allocation-free rule: __device__ globals).
static __device__ float g_q[BH*SEQ*HDIM];
static __device__ float g_k[BH*SEQ*HDIM];
static __device__ float g_v[BH*SEQ*HDIM];
static __device__ float g_o[BATCH*SEQ*EMB];
static __device__ float g_m[BH*SEQ];
static __device__ float g_l[BH*SEQ];

// ---------------------------------------------------------------------------
// tf32 helpers
// ---------------------------------------------------------------------------
__device__ __forceinline__ uint32_t f2tf(float x) {
    uint32_t r;
    asm("cvt.rna.tf32.f32 %0, %1;" : "=r"(r) : "f"(x));
    return r;
}
__device__ __forceinline__ void mma8(float* c, const uint32_t* a,
                                     uint32_t b0, uint32_t b1) {
    asm volatile(
        "mma.sync.aligned.m16n8k8.row.col.f32.tf32.tf32.f32 "
        "{%0,%1,%2,%3}, {%4,%5,%6,%7}, {%8,%9}, {%0,%1,%2,%3};"
        : "+f"(c[0]), "+f"(c[1]), "+f"(c[2]), "+f"(c[3])
        : "r"(a[0]), "r"(a[1]), "r"(a[2]), "r"(a[3]), "r"(b0), "r"(b1));
}

// ---------------------------------------------------------------------------
// GEMM: C[M=8192, N=512] = X @ W + bias (fp32 FFMA; proven correct)
// permute=1: write per-head [b,h,l,d]; permute=0: row-major [m,n].
// ---------------------------------------------------------------------------
__global__ __launch_bounds__(256) void proj_kernel(
    const float* __restrict__ X, const float* __restrict__ W,
    const float* __restrict__ bias, float* __restrict__ Out, int permute)
{
    __shared__ float As[16][132];
    __shared__ float Bs[16][68];
    const int t  = threadIdx.x;
    const int tx = t & 15, ty = t >> 4;
    const int m0 = blockIdx.y * 128;
    const int n0 = blockIdx.x * 64;

    float acc[8][4];
    #pragma unroll
    for (int i = 0; i < 8; i++)
        #pragma unroll
        for (int j = 0; j < 4; j++) acc[i][j] = 0.f;

    for (int k0 = 0; k0 < EMB; k0 += 16) {
        #pragma unroll
        for (int s = 0; s < 2; s++) {
            int idx = t + s * 256;
            int row = idx >> 2;
            int k4  = (idx & 3) << 2;
            float4 v = *(const float4*)(X + (size_t)(m0 + row) * EMB + k0 + k4);
            As[k4 + 0][row] = v.x; As[k4 + 1][row] = v.y;
            As[k4 + 2][row] = v.z; As[k4 + 3][row] = v.w;
        }
        {
            int row = t >> 4;
            int n4  = (t & 15) << 2;
            *(float4*)&Bs[row][n4] =
                *(const float4*)(W + (size_t)(k0 + row) * EMB + n0 + n4);
        }
        __syncthreads();
        #pragma unroll
        for (int kk = 0; kk < 16; kk++) {
            float a[8], b[4];
            *(float4*)(a)     = *(float4*)&As[kk][ty * 8];
            *(float4*)(a + 4) = *(float4*)&As[kk][ty * 8 + 4];
            *(float4*)(b)     = *(float4*)&Bs[kk][tx * 4];
            #pragma unroll
            for (int i = 0; i < 8; i++)
                #pragma unroll
                for (int j = 0; j < 4; j++)
                    acc[i][j] = fmaf(a[i], b[j], acc[i][j]);
        }
        __syncthreads();
    }

    #pragma unroll
    for (int i = 0; i < 8; i++) {
        int m = m0 + ty * 8 + i;
        #pragma unroll
        for (int j = 0; j < 4; j++) {
            int n = n0 + tx * 4 + j;
            float v = acc[i][j] + bias[n];
            if (permute) {
                int b_ = m >> 11, l = m & 2047;
                int h  = n >> 6,  d = n & 63;
                Out[(((size_t)(b_ * HEADS + h) * SEQ + l) << 6) + d] = v;
            } else {
                Out[(size_t)m * EMB + n] = v;
            }
        }
    }
}

// ---------------------------------------------------------------------------
// Scores + online softmax stats (tf32 tensor cores).
// Block: 128 q-rows (one full-row strip), all 2048 k-cols in 32 tiles of 64.
// 8 warps, each owns 16 q-rows x 64 cols (one m16 tile, 8 n8 tiles).
// Writes raw masked scores S = qk/8 + grm (or -1e30) into the attn region,
// and per-row (max, sum-exp) to g_m/g_l.
// ---------------------------------------------------------------------------
#define KSTR 76
__global__ __launch_bounds__(256, 2) void scores_stats_kernel(
    const int* __restrict__ mask, const float* __restrict__ grm,
    float* __restrict__ attn)
{
    __shared__ float Ks[64 * KSTR];          // K-tile [kcol][d], tf32 bits
    const int t = threadIdx.x, lane = t & 31, w = t >> 5;
    const int g = lane >> 2, tg = lane & 3;
    const int z = blockIdx.y, b_ = z >> 3;
    const int m0 = blockIdx.x * 128;
    const float* Q  = g_q + (size_t)z * SEQ * HDIM;
    const float* Kg = g_k + (size_t)z * SEQ * HDIM;
    const int rowA = m0 + w * 16 + g;        // this thread: rows rowA, rowA+8

    // Hoist A fragments (16 q-rows x full d=64) into registers, tf32.
    uint32_t a[8][4];
    #pragma unroll
    for (int ks = 0; ks < 8; ks++) {
        a[ks][0] = f2tf(Q[(size_t)rowA       * 64 + 8 * ks + tg]);
        a[ks][1] = f2tf(Q[(size_t)(rowA + 8) * 64 + 8 * ks + tg]);
        a[ks][2] = f2tf(Q[(size_t)rowA       * 64 + 8 * ks + tg + 4]);
        a[ks][3] = f2tf(Q[(size_t)(rowA + 8) * 64 + 8 * ks + tg + 4]);
    }

    float m0r = BIG_NEG, m1r = BIG_NEG, l0r = 0.f, l1r = 0.f;
    float* outS = attn + (size_t)z * SEQ * SEQ;

    for (int nt = 0; nt < 32; nt++) {
        // Load K tile (64 kcols x 64 d) -> smem, tf32
        #pragma unroll
        for (int r = 0; r < 4; r++) {
            int row = r * 16 + (t >> 4), c4 = (t & 15) * 4;
            float4 v = *(const float4*)&Kg[(size_t)(nt * 64 + row) * 64 + c4];
            Ks[row * KSTR + c4 + 0] = __uint_as_float(f2tf(v.x));
            Ks[row * KSTR + c4 + 1] = __uint_as_float(f2tf(v.y));
            Ks[row * KSTR + c4 + 2] = __uint_as_float(f2tf(v.z));
            Ks[row * KSTR + c4 + 3] = __uint_as_float(f2tf(v.w));
        }
        __syncthreads();

        float acc[8][4];
        #pragma unroll
        for (int j = 0; j < 8; j++)
            #pragma unroll
            for (int i = 0; i < 4; i++) acc[j][i] = 0.f;

        #pragma unroll
        for (int ks = 0; ks < 8; ks++) {
            #pragma unroll
            for (int j = 0; j < 8; j++) {
                uint32_t b0 = __float_as_uint(Ks[(8 * j + g) * KSTR + 8 * ks + tg]);
                uint32_t b1 = __float_as_uint(Ks[(8 * j + g) * KSTR + 8 * ks + tg + 4]);
                mma8(acc[j], a[ks], b0, b1);
            }
        }

        // Epilogue: scale + grm + mask, write S, track row stats.
        float mx0 = BIG_NEG, mx1 = BIG_NEG;
        #pragma unroll
        for (int j = 0; j < 8; j++) {
            int kc = nt * 64 + 8 * j + 2 * tg;
            int2   mk0 = *(const int2*)  &mask[((size_t)b_ * SEQ + rowA)     * SEQ + kc];
            int2   mk1 = *(const int2*)  &mask[((size_t)b_ * SEQ + rowA + 8) * SEQ + kc];
            float2 gr0 = *(const float2*)&grm[(size_t)rowA       * SEQ + kc];
            float2 gr1 = *(const float2*)&grm[(size_t)(rowA + 8) * SEQ + kc];
            float s00 = mk0.x ? acc[j][0] * 0.125f + gr0.x : BIG_NEG;
            float s01 = mk0.y ? acc[j][1] * 0.125f + gr0.y : BIG_NEG;
            float s10 = mk1.x ? acc[j][2] * 0.125f + gr1.x : BIG_NEG;
            float s11 = mk1.y ? acc[j][3] * 0.125f + gr1.y : BIG_NEG;
            acc[j][0] = s00; acc[j][1] = s01; acc[j][2] = s10; acc[j][3] = s11;
            *(float2*)&outS[(size_t)rowA       * SEQ + kc] = make_float2(s00, s01);
            *(float2*)&outS[(size_t)(rowA + 8) * SEQ + kc] = make_float2(s10, s11);
            mx0 = fmaxf(mx0, fmaxf(s00, s01));
            mx1 = fmaxf(mx1, fmaxf(s10, s11));
        }
        mx0 = fmaxf(mx0, __shfl_xor_sync(0xffffffffu, mx0, 1));
        mx0 = fmaxf(mx0, __shfl_xor_sync(0xffffffffu, mx0, 2));
        mx1 = fmaxf(mx1, __shfl_xor_sync(0xffffffffu, mx1, 1));
        mx1 = fmaxf(mx1, __shfl_xor_sync(0xffffffffu, mx1, 2));
        float mn0 = fmaxf(m0r, mx0), mn1 = fmaxf(m1r, mx1);
        float su0 = 0.f, su1 = 0.f;
        #pragma unroll
        for (int j = 0; j < 8; j++) {
            su0 += __expf(acc[j][0] - mn0) + __expf(acc[j][1] - mn0);
            su1 += __expf(acc[j][2] - mn1) + __expf(acc[j][3] - mn1);
        }
        su0 += __shfl_xor_sync(0xffffffffu, su0, 1);
        su0 += __shfl_xor_sync(0xffffffffu, su0, 2);
        su1 += __shfl_xor_sync(0xffffffffu, su1, 1);
        su1 += __shfl_xor_sync(0xffffffffu, su1, 2);
        l0r = l0r * __expf(m0r - mn0) + su0;  m0r = mn0;
        l1r = l1r * __expf(m1r - mn1) + su1;  m1r = mn1;
        __syncthreads();
    }

    if (tg == 0) {
        g_m[(size_t)z * SEQ + rowA]     = m0r;
        g_l[(size_t)z * SEQ + rowA]     = l0r;
        g_m[(size_t)z * SEQ + rowA + 8] = m1r;
        g_l[(size_t)z * SEQ + rowA + 8] = l1r;
    }
}

// ---------------------------------------------------------------------------
// Fused: read raw S, normalize p = exp(s-m)/l, write P (attention_weights),
// and compute O = P @ V with tf32 mma. Block: 128 q x 64 d; 8 warps as
// 4 row-groups(32q) x 2 col-groups(32d); k-tiles of 32.
// ---------------------------------------------------------------------------
#define ASTR 36
#define VSTR 72
__global__ __launch_bounds__(256, 2) void av_fused_kernel(float* __restrict__ attn)
{
    __shared__ float As[128 * ASTR];          // tf32 bits of P tile [q][k]
    __shared__ float Vs[32 * VSTR];           // tf32 bits of V tile [k][d]
    __shared__ float ms[128], ils[128];
    const int t = threadIdx.x, lane = t & 31, w = t >> 5;
    const int g = lane >> 2, tg = lane & 3;
    const int wr = w >> 1, wc = w & 1;
    const int z = blockIdx.y, b_ = z >> 3, h = z & 7;
    const int m0 = blockIdx.x * 128;
    float* S = attn + (size_t)z * SEQ * SEQ;
    const float* V = g_v + (size_t)z * SEQ * HDIM;

    if (t < 128) {
        ms[t]  = g_m[(size_t)z * SEQ + m0 + t];
        ils[t] = 1.0f / g_l[(size_t)z * SEQ + m0 + t];
    }
    __syncthreads();

    float acc[2][4][4];
    #pragma unroll
    for (int mi = 0; mi < 2; mi++)
        #pragma unroll
        for (int j = 0; j < 4; j++)
            #pragma unroll
            for (int i = 0; i < 4; i++) acc[mi][j][i] = 0.f;

    for (int kt = 0; kt < 64; kt++) {
        const int k0 = kt * 32;
        // Load S strip 128x32, normalize, write P back, stage tf32 in smem.
        #pragma unroll
        for (int it = 0; it < 4; it++) {
            int q = it * 32 + (t >> 3), c4 = (t & 7) * 4;
            size_t off = (size_t)(m0 + q) * SEQ + k0 + c4;
            float4 s = *(const float4*)&S[off];
            float m = ms[q], il = ils[q];
            float4 p;
            p.x = __expf(s.x - m) * il;
            p.y = __expf(s.y - m) * il;
            p.z = __expf(s.z - m) * il;
            p.w = __expf(s.w - m) * il;
            *(float4*)&S[off] = p;
            As[q * ASTR + c4 + 0] = __uint_as_float(f2tf(p.x));
            As[q * ASTR + c4 + 1] = __uint_as_float(f2tf(p.y));
            As[q * ASTR + c4 + 2] = __uint_as_float(f2tf(p.z));
            As[q * ASTR + c4 + 3] = __uint_as_float(f2tf(p.w));
        }
        // Load V tile 32x64
        #pragma unroll
        for (int s2 = 0; s2 < 2; s2++) {
            int row = s2 * 16 + (t >> 4), c4 = (t & 15) * 4;
            float4 v = *(const float4*)&V[(size_t)(k0 + row) * HDIM + c4];
            Vs[row * VSTR + c4 + 0] = __uint_as_float(f2tf(v.x));
            Vs[row * VSTR + c4 + 1] = __uint_as_float(f2tf(v.y));
            Vs[row * VSTR + c4 + 2] = __uint_as_float(f2tf(v.z));
            Vs[row * VSTR + c4 + 3] = __uint_as_float(f2tf(v.w));
        }
        __syncthreads();

        #pragma unroll
        for (int ks = 0; ks < 4; ks++) {
            uint32_t af[2][4];
            #pragma unroll
            for (int mi = 0; mi < 2; mi++) {
                int q = wr * 32 + mi * 16 + g;
                af[mi][0] = __float_as_uint(As[q * ASTR + 8 * ks + tg]);
                af[mi][1] = __float_as_uint(As[(q + 8) * ASTR + 8 * ks + tg]);
                af[mi][2] = __float_as_uint(As[q * ASTR + 8 * ks + tg + 4]);
                af[mi][3] = __float_as_uint(As[(q + 8) * ASTR + 8 * ks + tg + 4]);
            }
            #pragma unroll
            for (int j = 0; j < 4; j++) {
                uint32_t b0 = __float_as_uint(Vs[(8 * ks + tg)     * VSTR + wc * 32 + 8 * j + g]);
                uint32_t b1 = __float_as_uint(Vs[(8 * ks + tg + 4) * VSTR + wc * 32 + 8 * j + g]);
                mma8(acc[0][j], af[0], b0, b1);
                mma8(acc[1][j], af[1], b0, b1);
            }
        }
        __syncthreads();
    }

    // Epilogue: O -> g_o[b][l][h*64 + d]
    #pragma unroll
    for (int mi = 0; mi < 2; mi++) {
        int q0 = m0 + wr * 32 + mi * 16 + g;
        #pragma unroll
        for (int j = 0; j < 4; j++) {
            int d = h * 64 + wc * 32 + 8 * j + 2 * tg;
            *(float2*)&g_o[((size_t)b_ * SEQ + q0)     * EMB + d] =
                make_float2(acc[mi][j][0], acc[mi][j][1]);
            *(float2*)&g_o[((size_t)b_ * SEQ + q0 + 8) * EMB + d] =
                make_float2(acc[mi][j][2], acc[mi][j][3]);
        }
    }
}

// ---------------------------------------------------------------------------
extern "C" void kernel_launch(void* const* d_in, const int* in_sizes, int n_in,
                              void* d_out, int out_size)
{
    const float* query = (const float*)d_in[0];
    const float* key_  = (const float*)d_in[1];
    const float* value = (const float*)d_in[2];
    const int*   mask  = (const int*)  d_in[3];
    const float* grm   = (const float*)d_in[4];
    const float* Wq = (const float*)d_in[5];
    const float* bq = (const float*)d_in[6];
    const float* Wk = (const float*)d_in[7];
    const float* bk = (const float*)d_in[8];
    const float* Wv = (const float*)d_in[9];
    const float* bv = (const float*)d_in[10];
    const float* Wo = (const float*)d_in[11];
    const float* bo = (const float*)d_in[12];

    float* out  = (float*)d_out;                       // [B, L, E]
    float* attn = out + (size_t)BATCH * SEQ * EMB;     // [B, H, L, L]

    float *q_, *k_, *v_, *o_;
    cudaGetSymbolAddress((void**)&q_, g_q);
    cudaGetSymbolAddress((void**)&k_, g_k);
    cudaGetSymbolAddress((void**)&v_, g_v);
    cudaGetSymbolAddress((void**)&o_, g_o);

    dim3 gProj(EMB / 64, MTOT / 128);        // (8, 64)
    proj_kernel<<<gProj, 256>>>(query, Wq, bq, q_, 1);
    proj_kernel<<<gProj, 256>>>(key_,  Wk, bk, k_, 1);
    proj_kernel<<<gProj, 256>>>(value, Wv, bv, v_, 1);

    dim3 gSc(SEQ / 128, BH);                 // (16, 32)
    scores_stats_kernel<<<gSc, 256>>>(mask, grm, attn);

    dim3 gAv(SEQ / 128, BH);                 // (16, 32)
    av_fused_kernel<<<gAv, 256>>>(attn);

    proj_kernel<<<gProj, 256>>>(o_, Wo, bo, out, 0);
}

// round 4
// speedup vs baseline: 1.3979x; 1.0677x over previous
#include <cuda_runtime.h>
#include <cstdint>

#define BATCH 4
#define HEADS 8
#define SEQ   2048
#define HDIM  64
#define EMB   512
#define BH    (BATCH*HEADS)
#define MTOT  (BATCH*SEQ)
#define BIG_NEG (-1e30f)

// Scratch (allocation-free rule: __device__ globals).
static __device__ float g_q[BH*SEQ*HDIM];
static __device__ float g_k[BH*SEQ*HDIM];
static __device__ float g_v[BH*SEQ*HDIM];
static __device__ float g_o[BATCH*SEQ*EMB];

// ---------------------------------------------------------------------------
// tf32 helpers (proven Round 2)
// ---------------------------------------------------------------------------
__device__ __forceinline__ uint32_t f2tf(float x) {
    uint32_t r;
    asm("cvt.rna.tf32.f32 %0, %1;" : "=r"(r) : "f"(x));
    return r;
}
__device__ __forceinline__ void mma8(float* c, const uint32_t* a,
                                     uint32_t b0, uint32_t b1) {
    asm volatile(
        "mma.sync.aligned.m16n8k8.row.col.f32.tf32.tf32.f32 "
        "{%0,%1,%2,%3}, {%4,%5,%6,%7}, {%8,%9}, {%0,%1,%2,%3};"
        : "+f"(c[0]), "+f"(c[1]), "+f"(c[2]), "+f"(c[3])
        : "r"(a[0]), "r"(a[1]), "r"(a[2]), "r"(a[3]), "r"(b0), "r"(b1));
}

// ---------------------------------------------------------------------------
// tf32 projection GEMM: C[8192,512] = X @ W + bias.
// BM=128, BN=64, BK=32. 8 warps = 4 row-groups x 2 col-groups; each warp
// 32q x 32n (2 m16 tiles x 4 n8 tiles).
// permute=1: write per-head [b,h,l,d]; permute=0: row-major [m,n].
// ---------------------------------------------------------------------------
#define XSTR 36
#define WSTR 68
__global__ __launch_bounds__(256, 2) void proj_tf32_kernel(
    const float* __restrict__ X, const float* __restrict__ W,
    const float* __restrict__ bias, float* __restrict__ Out, int permute)
{
    __shared__ float Xs[128 * XSTR];   // [q][k], tf32 bits
    __shared__ float Ws[32 * WSTR];    // [k][n], tf32 bits
    const int t = threadIdx.x, lane = t & 31, w = t >> 5;
    const int g = lane >> 2, tg = lane & 3;
    const int wr = w >> 1, wc = w & 1;
    const int m0 = blockIdx.y * 128;
    const int n0 = blockIdx.x * 64;

    float acc[2][4][4];
    #pragma unroll
    for (int mi = 0; mi < 2; mi++)
        #pragma unroll
        for (int j = 0; j < 4; j++)
            #pragma unroll
            for (int i = 0; i < 4; i++) acc[mi][j][i] = 0.f;

    for (int k0 = 0; k0 < EMB; k0 += 32) {
        #pragma unroll
        for (int it = 0; it < 4; it++) {
            int q = it * 32 + (t >> 3), c4 = (t & 7) * 4;
            float4 v = *(const float4*)&X[(size_t)(m0 + q) * EMB + k0 + c4];
            Xs[q * XSTR + c4 + 0] = __uint_as_float(f2tf(v.x));
            Xs[q * XSTR + c4 + 1] = __uint_as_float(f2tf(v.y));
            Xs[q * XSTR + c4 + 2] = __uint_as_float(f2tf(v.z));
            Xs[q * XSTR + c4 + 3] = __uint_as_float(f2tf(v.w));
        }
        #pragma unroll
        for (int s2 = 0; s2 < 2; s2++) {
            int row = s2 * 16 + (t >> 4), c4 = (t & 15) * 4;
            float4 v = *(const float4*)&W[(size_t)(k0 + row) * EMB + n0 + c4];
            Ws[row * WSTR + c4 + 0] = __uint_as_float(f2tf(v.x));
            Ws[row * WSTR + c4 + 1] = __uint_as_float(f2tf(v.y));
            Ws[row * WSTR + c4 + 2] = __uint_as_float(f2tf(v.z));
            Ws[row * WSTR + c4 + 3] = __uint_as_float(f2tf(v.w));
        }
        __syncthreads();

        #pragma unroll
        for (int ks = 0; ks < 4; ks++) {
            uint32_t af[2][4];
            #pragma unroll
            for (int mi = 0; mi < 2; mi++) {
                int q = wr * 32 + mi * 16 + g;
                af[mi][0] = __float_as_uint(Xs[q * XSTR + 8 * ks + tg]);
                af[mi][1] = __float_as_uint(Xs[(q + 8) * XSTR + 8 * ks + tg]);
                af[mi][2] = __float_as_uint(Xs[q * XSTR + 8 * ks + tg + 4]);
                af[mi][3] = __float_as_uint(Xs[(q + 8) * XSTR + 8 * ks + tg + 4]);
            }
            #pragma unroll
            for (int j = 0; j < 4; j++) {
                uint32_t b0 = __float_as_uint(Ws[(8 * ks + tg)     * WSTR + wc * 32 + 8 * j + g]);
                uint32_t b1 = __float_as_uint(Ws[(8 * ks + tg + 4) * WSTR + wc * 32 + 8 * j + g]);
                mma8(acc[0][j], af[0], b0, b1);
                mma8(acc[1][j], af[1], b0, b1);
            }
        }
        __syncthreads();
    }

    #pragma unroll
    for (int mi = 0; mi < 2; mi++) {
        int q0 = m0 + wr * 32 + mi * 16 + g;
        #pragma unroll
        for (int j = 0; j < 4; j++) {
            int n = n0 + wc * 32 + 8 * j + 2 * tg;
            float b0 = bias[n], b1 = bias[n + 1];
            float2 v0 = make_float2(acc[mi][j][0] + b0, acc[mi][j][1] + b1);
            float2 v1 = make_float2(acc[mi][j][2] + b0, acc[mi][j][3] + b1);
            if (permute) {
                int b_ = q0 >> 11, h = n >> 6, d = n & 63;
                int l0 = q0 & 2047;
                size_t base = ((size_t)(b_ * HEADS + h) * SEQ);
                *(float2*)&Out[((base + l0)     << 6) + d] = v0;
                *(float2*)&Out[((base + l0 + 8) << 6) + d] = v1;
            } else {
                *(float2*)&Out[(size_t)q0 * EMB + n]       = v0;
                *(float2*)&Out[(size_t)(q0 + 8) * EMB + n] = v1;
            }
        }
    }
}

// ---------------------------------------------------------------------------
// Fused flash attention: per block 128 q-rows of one head z.
// Phase A: stream K tiles (32 kcols), tf32 mma -> online (m, l) stats only.
// Phase B: recompute S tiles, p = exp(s-m)/l, write P (attention output)
//          once, and accumulate O = P @ V with tf32 mma.
// Each warp owns 16 q-rows end-to-end (stats live in registers).
// ---------------------------------------------------------------------------
#define KSTR 76
#define VSTR 72
#define PSTR 36
__global__ __launch_bounds__(256, 2) void flash_kernel(
    const int* __restrict__ mask, const float* __restrict__ grm,
    float* __restrict__ attn)
{
    __shared__ float Ks[32 * KSTR];    // 32 kcols x 64 d, tf32 bits
    __shared__ float Vs[32 * VSTR];    // 32 k x 64 d, tf32 bits
    __shared__ float Ps[128 * PSTR];   // 128 q x 32 k, tf32 bits
    const int t = threadIdx.x, lane = t & 31, w = t >> 5;
    const int g = lane >> 2, tg = lane & 3;
    const int z = blockIdx.y, b_ = z >> 3, h = z & 7;
    const int m0 = blockIdx.x * 128;
    const float* Q  = g_q + (size_t)z * SEQ * HDIM;
    const float* Kg = g_k + (size_t)z * SEQ * HDIM;
    const float* V  = g_v + (size_t)z * SEQ * HDIM;
    const int rowA = m0 + w * 16 + g;     // this thread: rows rowA, rowA+8
    const int rql  = w * 16 + g;
    float* outP = attn + (size_t)z * SEQ * SEQ;

    // Hoist Q fragments (16 q-rows x d=64) into registers, tf32.
    uint32_t a[8][4];
    #pragma unroll
    for (int ks = 0; ks < 8; ks++) {
        a[ks][0] = f2tf(Q[(size_t)rowA       * 64 + 8 * ks + tg]);
        a[ks][1] = f2tf(Q[(size_t)(rowA + 8) * 64 + 8 * ks + tg]);
        a[ks][2] = f2tf(Q[(size_t)rowA       * 64 + 8 * ks + tg + 4]);
        a[ks][3] = f2tf(Q[(size_t)(rowA + 8) * 64 + 8 * ks + tg + 4]);
    }

    float m0r = BIG_NEG, m1r = BIG_NEG, l0r = 0.f, l1r = 0.f;

    // ---------------- Phase A: stats ----------------
    for (int nt = 0; nt < 64; nt++) {
        #pragma unroll
        for (int s2 = 0; s2 < 2; s2++) {
            int row = s2 * 16 + (t >> 4), c4 = (t & 15) * 4;
            float4 v = *(const float4*)&Kg[(size_t)(nt * 32 + row) * 64 + c4];
            Ks[row * KSTR + c4 + 0] = __uint_as_float(f2tf(v.x));
            Ks[row * KSTR + c4 + 1] = __uint_as_float(f2tf(v.y));
            Ks[row * KSTR + c4 + 2] = __uint_as_float(f2tf(v.z));
            Ks[row * KSTR + c4 + 3] = __uint_as_float(f2tf(v.w));
        }
        __syncthreads();

        float acc[4][4];
        #pragma unroll
        for (int j = 0; j < 4; j++)
            #pragma unroll
            for (int i = 0; i < 4; i++) acc[j][i] = 0.f;
        #pragma unroll
        for (int ks = 0; ks < 8; ks++)
            #pragma unroll
            for (int j = 0; j < 4; j++) {
                uint32_t b0 = __float_as_uint(Ks[(8 * j + g) * KSTR + 8 * ks + tg]);
                uint32_t b1 = __float_as_uint(Ks[(8 * j + g) * KSTR + 8 * ks + tg + 4]);
                mma8(acc[j], a[ks], b0, b1);
            }

        float mx0 = BIG_NEG, mx1 = BIG_NEG;
        #pragma unroll
        for (int j = 0; j < 4; j++) {
            int kc = nt * 32 + 8 * j + 2 * tg;
            int2   mk0 = *(const int2*)  &mask[((size_t)b_ * SEQ + rowA)     * SEQ + kc];
            int2   mk1 = *(const int2*)  &mask[((size_t)b_ * SEQ + rowA + 8) * SEQ + kc];
            float2 gr0 = *(const float2*)&grm[(size_t)rowA       * SEQ + kc];
            float2 gr1 = *(const float2*)&grm[(size_t)(rowA + 8) * SEQ + kc];
            acc[j][0] = mk0.x ? acc[j][0] * 0.125f + gr0.x : BIG_NEG;
            acc[j][1] = mk0.y ? acc[j][1] * 0.125f + gr0.y : BIG_NEG;
            acc[j][2] = mk1.x ? acc[j][2] * 0.125f + gr1.x : BIG_NEG;
            acc[j][3] = mk1.y ? acc[j][3] * 0.125f + gr1.y : BIG_NEG;
            mx0 = fmaxf(mx0, fmaxf(acc[j][0], acc[j][1]));
            mx1 = fmaxf(mx1, fmaxf(acc[j][2], acc[j][3]));
        }
        mx0 = fmaxf(mx0, __shfl_xor_sync(0xffffffffu, mx0, 1));
        mx0 = fmaxf(mx0, __shfl_xor_sync(0xffffffffu, mx0, 2));
        mx1 = fmaxf(mx1, __shfl_xor_sync(0xffffffffu, mx1, 1));
        mx1 = fmaxf(mx1, __shfl_xor_sync(0xffffffffu, mx1, 2));
        float mn0 = fmaxf(m0r, mx0), mn1 = fmaxf(m1r, mx1);
        float su0 = 0.f, su1 = 0.f;
        #pragma unroll
        for (int j = 0; j < 4; j++) {
            su0 += (acc[j][0] > -1e29f) ? __expf(acc[j][0] - mn0) : 0.f;
            su0 += (acc[j][1] > -1e29f) ? __expf(acc[j][1] - mn0) : 0.f;
            su1 += (acc[j][2] > -1e29f) ? __expf(acc[j][2] - mn1) : 0.f;
            su1 += (acc[j][3] > -1e29f) ? __expf(acc[j][3] - mn1) : 0.f;
        }
        su0 += __shfl_xor_sync(0xffffffffu, su0, 1);
        su0 += __shfl_xor_sync(0xffffffffu, su0, 2);
        su1 += __shfl_xor_sync(0xffffffffu, su1, 1);
        su1 += __shfl_xor_sync(0xffffffffu, su1, 2);
        l0r = (mn0 > -1e29f) ? l0r * __expf(m0r - mn0) + su0 : 0.f;
        l1r = (mn1 > -1e29f) ? l1r * __expf(m1r - mn1) + su1 : 0.f;
        m0r = mn0;  m1r = mn1;
        __syncthreads();
    }

    const float il0 = 1.0f / l0r, il1 = 1.0f / l1r;

    // ---------------- Phase B: P write + O = P @ V ----------------
    float acc_o[8][4];
    #pragma unroll
    for (int j = 0; j < 8; j++)
        #pragma unroll
        for (int i = 0; i < 4; i++) acc_o[j][i] = 0.f;

    for (int nt = 0; nt < 64; nt++) {
        #pragma unroll
        for (int s2 = 0; s2 < 2; s2++) {
            int row = s2 * 16 + (t >> 4), c4 = (t & 15) * 4;
            float4 kv = *(const float4*)&Kg[(size_t)(nt * 32 + row) * 64 + c4];
            Ks[row * KSTR + c4 + 0] = __uint_as_float(f2tf(kv.x));
            Ks[row * KSTR + c4 + 1] = __uint_as_float(f2tf(kv.y));
            Ks[row * KSTR + c4 + 2] = __uint_as_float(f2tf(kv.z));
            Ks[row * KSTR + c4 + 3] = __uint_as_float(f2tf(kv.w));
            float4 vv = *(const float4*)&V[(size_t)(nt * 32 + row) * 64 + c4];
            Vs[row * VSTR + c4 + 0] = __uint_as_float(f2tf(vv.x));
            Vs[row * VSTR + c4 + 1] = __uint_as_float(f2tf(vv.y));
            Vs[row * VSTR + c4 + 2] = __uint_as_float(f2tf(vv.z));
            Vs[row * VSTR + c4 + 3] = __uint_as_float(f2tf(vv.w));
        }
        __syncthreads();

        // Recompute S tile
        float accs[4][4];
        #pragma unroll
        for (int j = 0; j < 4; j++)
            #pragma unroll
            for (int i = 0; i < 4; i++) accs[j][i] = 0.f;
        #pragma unroll
        for (int ks = 0; ks < 8; ks++)
            #pragma unroll
            for (int j = 0; j < 4; j++) {
                uint32_t b0 = __float_as_uint(Ks[(8 * j + g) * KSTR + 8 * ks + tg]);
                uint32_t b1 = __float_as_uint(Ks[(8 * j + g) * KSTR + 8 * ks + tg + 4]);
                mma8(accs[j], a[ks], b0, b1);
            }

        // p = exp(s - m) / l; write P; stage tf32(p) for PV mma
        #pragma unroll
        for (int j = 0; j < 4; j++) {
            int kc = nt * 32 + 8 * j + 2 * tg;
            int2   mk0 = *(const int2*)  &mask[((size_t)b_ * SEQ + rowA)     * SEQ + kc];
            int2   mk1 = *(const int2*)  &mask[((size_t)b_ * SEQ + rowA + 8) * SEQ + kc];
            float2 gr0 = *(const float2*)&grm[(size_t)rowA       * SEQ + kc];
            float2 gr1 = *(const float2*)&grm[(size_t)(rowA + 8) * SEQ + kc];
            float p00 = mk0.x ? __expf(accs[j][0] * 0.125f + gr0.x - m0r) * il0 : 0.f;
            float p01 = mk0.y ? __expf(accs[j][1] * 0.125f + gr0.y - m0r) * il0 : 0.f;
            float p10 = mk1.x ? __expf(accs[j][2] * 0.125f + gr1.x - m1r) * il1 : 0.f;
            float p11 = mk1.y ? __expf(accs[j][3] * 0.125f + gr1.y - m1r) * il1 : 0.f;
            *(float2*)&outP[(size_t)rowA       * SEQ + kc] = make_float2(p00, p01);
            *(float2*)&outP[(size_t)(rowA + 8) * SEQ + kc] = make_float2(p10, p11);
            int c = 8 * j + 2 * tg;
            Ps[rql * PSTR + c]           = __uint_as_float(f2tf(p00));
            Ps[rql * PSTR + c + 1]       = __uint_as_float(f2tf(p01));
            Ps[(rql + 8) * PSTR + c]     = __uint_as_float(f2tf(p10));
            Ps[(rql + 8) * PSTR + c + 1] = __uint_as_float(f2tf(p11));
        }
        __syncwarp();   // Ps rows of this warp written by its own lanes only

        // O += P_tile @ V_tile  (16q x 64d per warp, k=32)
        #pragma unroll
        for (int ks = 0; ks < 4; ks++) {
            uint32_t af[4];
            af[0] = __float_as_uint(Ps[rql * PSTR + 8 * ks + tg]);
            af[1] = __float_as_uint(Ps[(rql + 8) * PSTR + 8 * ks + tg]);
            af[2] = __float_as_uint(Ps[rql * PSTR + 8 * ks + tg + 4]);
            af[3] = __float_as_uint(Ps[(rql + 8) * PSTR + 8 * ks + tg + 4]);
            #pragma unroll
            for (int j = 0; j < 8; j++) {
                uint32_t b0 = __float_as_uint(Vs[(8 * ks + tg)     * VSTR + 8 * j + g]);
                uint32_t b1 = __float_as_uint(Vs[(8 * ks + tg + 4) * VSTR + 8 * j + g]);
                mma8(acc_o[j], af, b0, b1);
            }
        }
        __syncthreads();
    }

    // Epilogue: O -> g_o[b][l][h*64 + d]
    #pragma unroll
    for (int j = 0; j < 8; j++) {
        int d = h * 64 + 8 * j + 2 * tg;
        *(float2*)&g_o[((size_t)b_ * SEQ + rowA)     * EMB + d] =
            make_float2(acc_o[j][0], acc_o[j][1]);
        *(float2*)&g_o[((size_t)b_ * SEQ + rowA + 8) * EMB + d] =
            make_float2(acc_o[j][2], acc_o[j][3]);
    }
}

// ---------------------------------------------------------------------------
extern "C" void kernel_launch(void* const* d_in, const int* in_sizes, int n_in,
                              void* d_out, int out_size)
{
    const float* query = (const float*)d_in[0];
    const float* key_  = (const float*)d_in[1];
    const float* value = (const float*)d_in[2];
    const int*   mask  = (const int*)  d_in[3];
    const float* grm   = (const float*)d_in[4];
    const float* Wq = (const float*)d_in[5];
    const float* bq = (const float*)d_in[6];
    const float* Wk = (const float*)d_in[7];
    const float* bk = (const float*)d_in[8];
    const float* Wv = (const float*)d_in[9];
    const float* bv = (const float*)d_in[10];
    const float* Wo = (const float*)d_in[11];
    const float* bo = (const float*)d_in[12];

    float* out  = (float*)d_out;                       // [B, L, E]
    float* attn = out + (size_t)BATCH * SEQ * EMB;     // [B, H, L, L]

    float *q_, *k_, *v_, *o_;
    cudaGetSymbolAddress((void**)&q_, g_q);
    cudaGetSymbolAddress((void**)&k_, g_k);
    cudaGetSymbolAddress((void**)&v_, g_v);
    cudaGetSymbolAddress((void**)&o_, g_o);

    dim3 gProj(EMB / 64, MTOT / 128);        // (8, 64)
    proj_tf32_kernel<<<gProj, 256>>>(query, Wq, bq, q_, 1);
    proj_tf32_kernel<<<gProj, 256>>>(key_,  Wk, bk, k_, 1);
    proj_tf32_kernel<<<gProj, 256>>>(value, Wv, bv, v_, 1);

    dim3 gF(SEQ / 128, BH);                  // (16, 32)
    flash_kernel<<<gF, 256>>>(mask, grm, attn);

    proj_tf32_kernel<<<gProj, 256>>>(o_, Wo, bo, out, 0);
}

// round 5
// speedup vs baseline: 1.3980x; 1.0000x over previous
#include <cuda_runtime.h>
#include <cstdint>

#define BATCH 4
#define HEADS 8
#define SEQ   2048
#define HDIM  64
#define EMB   512
#define BH    (BATCH*HEADS)
#define MTOT  (BATCH*SEQ)
#define BIG_NEG (-1e30f)

// Scratch (allocation-free rule: __device__ globals).
static __device__ float g_q[BH*SEQ*HDIM];
static __device__ float g_k[BH*SEQ*HDIM];
static __device__ float g_v[BH*SEQ*HDIM];
static __device__ float g_o[BATCH*SEQ*EMB];

// ---------------------------------------------------------------------------
// tf32 helpers (proven Round 2)
// ---------------------------------------------------------------------------
__device__ __forceinline__ uint32_t f2tf(float x) {
    uint32_t r;
    asm("cvt.rna.tf32.f32 %0, %1;" : "=r"(r) : "f"(x));
    return r;
}
__device__ __forceinline__ void mma8(float* c, const uint32_t* a,
                                     uint32_t b0, uint32_t b1) {
    asm volatile(
        "mma.sync.aligned.m16n8k8.row.col.f32.tf32.tf32.f32 "
        "{%0,%1,%2,%3}, {%4,%5,%6,%7}, {%8,%9}, {%0,%1,%2,%3};"
        : "+f"(c[0]), "+f"(c[1]), "+f"(c[2]), "+f"(c[3])
        : "r"(a[0]), "r"(a[1]), "r"(a[2]), "r"(a[3]), "r"(b0), "r"(b1));
}

// ---------------------------------------------------------------------------
// tf32 projection GEMM: C[8192,512] = X @ W + bias.
// BM=128, BN=64, BK=32. 8 warps = 4 row-groups x 2 col-groups; each warp
// 32q x 32n (2 m16 tiles x 4 n8 tiles).
// permute=1: write per-head [b,h,l,d]; permute=0: row-major [m,n].
// ---------------------------------------------------------------------------
#define XSTR 36
#define WSTR 68
__global__ __launch_bounds__(256, 2) void proj_tf32_kernel(
    const float* __restrict__ X, const float* __restrict__ W,
    const float* __restrict__ bias, float* __restrict__ Out, int permute)
{
    __shared__ float Xs[128 * XSTR];   // [q][k], tf32 bits
    __shared__ float Ws[32 * WSTR];    // [k][n], tf32 bits
    const int t = threadIdx.x, lane = t & 31, w = t >> 5;
    const int g = lane >> 2, tg = lane & 3;
    const int wr = w >> 1, wc = w & 1;
    const int m0 = blockIdx.y * 128;
    const int n0 = blockIdx.x * 64;

    float acc[2][4][4];
    #pragma unroll
    for (int mi = 0; mi < 2; mi++)
        #pragma unroll
        for (int j = 0; j < 4; j++)
            #pragma unroll
            for (int i = 0; i < 4; i++) acc[mi][j][i] = 0.f;

    for (int k0 = 0; k0 < EMB; k0 += 32) {
        #pragma unroll
        for (int it = 0; it < 4; it++) {
            int q = it * 32 + (t >> 3), c4 = (t & 7) * 4;
            float4 v = *(const float4*)&X[(size_t)(m0 + q) * EMB + k0 + c4];
            Xs[q * XSTR + c4 + 0] = __uint_as_float(f2tf(v.x));
            Xs[q * XSTR + c4 + 1] = __uint_as_float(f2tf(v.y));
            Xs[q * XSTR + c4 + 2] = __uint_as_float(f2tf(v.z));
            Xs[q * XSTR + c4 + 3] = __uint_as_float(f2tf(v.w));
        }
        #pragma unroll
        for (int s2 = 0; s2 < 2; s2++) {
            int row = s2 * 16 + (t >> 4), c4 = (t & 15) * 4;
            float4 v = *(const float4*)&W[(size_t)(k0 + row) * EMB + n0 + c4];
            Ws[row * WSTR + c4 + 0] = __uint_as_float(f2tf(v.x));
            Ws[row * WSTR + c4 + 1] = __uint_as_float(f2tf(v.y));
            Ws[row * WSTR + c4 + 2] = __uint_as_float(f2tf(v.z));
            Ws[row * WSTR + c4 + 3] = __uint_as_float(f2tf(v.w));
        }
        __syncthreads();

        #pragma unroll
        for (int ks = 0; ks < 4; ks++) {
            uint32_t af[2][4];
            #pragma unroll
            for (int mi = 0; mi < 2; mi++) {
                int q = wr * 32 + mi * 16 + g;
                af[mi][0] = __float_as_uint(Xs[q * XSTR + 8 * ks + tg]);
                af[mi][1] = __float_as_uint(Xs[(q + 8) * XSTR + 8 * ks + tg]);
                af[mi][2] = __float_as_uint(Xs[q * XSTR + 8 * ks + tg + 4]);
                af[mi][3] = __float_as_uint(Xs[(q + 8) * XSTR + 8 * ks + tg + 4]);
            }
            #pragma unroll
            for (int j = 0; j < 4; j++) {
                uint32_t b0 = __float_as_uint(Ws[(8 * ks + tg)     * WSTR + wc * 32 + 8 * j + g]);
                uint32_t b1 = __float_as_uint(Ws[(8 * ks + tg + 4) * WSTR + wc * 32 + 8 * j + g]);
                mma8(acc[0][j], af[0], b0, b1);
                mma8(acc[1][j], af[1], b0, b1);
            }
        }
        __syncthreads();
    }

    #pragma unroll
    for (int mi = 0; mi < 2; mi++) {
        int q0 = m0 + wr * 32 + mi * 16 + g;
        #pragma unroll
        for (int j = 0; j < 4; j++) {
            int n = n0 + wc * 32 + 8 * j + 2 * tg;
            float b0 = bias[n], b1 = bias[n + 1];
            float2 v0 = make_float2(acc[mi][j][0] + b0, acc[mi][j][1] + b1);
            float2 v1 = make_float2(acc[mi][j][2] + b0, acc[mi][j][3] + b1);
            if (permute) {
                int b_ = q0 >> 11, h = n >> 6, d = n & 63;
                int l0 = q0 & 2047;
                size_t base = ((size_t)(b_ * HEADS + h) * SEQ);
                *(float2*)&Out[((base + l0)     << 6) + d] = v0;
                *(float2*)&Out[((base + l0 + 8) << 6) + d] = v1;
            } else {
                *(float2*)&Out[(size_t)q0 * EMB + n]       = v0;
                *(float2*)&Out[(size_t)(q0 + 8) * EMB + n] = v1;
            }
        }
    }
}

// ---------------------------------------------------------------------------
// Fused flash attention: per block 128 q-rows of one head z.
// Phase A: stream K tiles (32 kcols), tf32 mma -> online (m, l) stats only.
// Phase B: recompute S tiles, p = exp(s-m)/l, write P (attention output)
//          once, and accumulate O = P @ V with tf32 mma.
// Each warp owns 16 q-rows end-to-end (stats live in registers).
// ---------------------------------------------------------------------------
#define KSTR 76
#define VSTR 72
#define PSTR 36
__global__ __launch_bounds__(256, 2) void flash_kernel(
    const int* __restrict__ mask, const float* __restrict__ grm,
    float* __restrict__ attn)
{
    __shared__ float Ks[32 * KSTR];    // 32 kcols x 64 d, tf32 bits
    __shared__ float Vs[32 * VSTR];    // 32 k x 64 d, tf32 bits
    __shared__ float Ps[128 * PSTR];   // 128 q x 32 k, tf32 bits
    const int t = threadIdx.x, lane = t & 31, w = t >> 5;
    const int g = lane >> 2, tg = lane & 3;
    const int z = blockIdx.y, b_ = z >> 3, h = z & 7;
    const int m0 = blockIdx.x * 128;
    const float* Q  = g_q + (size_t)z * SEQ * HDIM;
    const float* Kg = g_k + (size_t)z * SEQ * HDIM;
    const float* V  = g_v + (size_t)z * SEQ * HDIM;
    const int rowA = m0 + w * 16 + g;     // this thread: rows rowA, rowA+8
    const int rql  = w * 16 + g;
    float* outP = attn + (size_t)z * SEQ * SEQ;

    // Hoist Q fragments (16 q-rows x d=64) into registers, tf32.
    uint32_t a[8][4];
    #pragma unroll
    for (int ks = 0; ks < 8; ks++) {
        a[ks][0] = f2tf(Q[(size_t)rowA       * 64 + 8 * ks + tg]);
        a[ks][1] = f2tf(Q[(size_t)(rowA + 8) * 64 + 8 * ks + tg]);
        a[ks][2] = f2tf(Q[(size_t)rowA       * 64 + 8 * ks + tg + 4]);
        a[ks][3] = f2tf(Q[(size_t)(rowA + 8) * 64 + 8 * ks + tg + 4]);
    }

    float m0r = BIG_NEG, m1r = BIG_NEG, l0r = 0.f, l1r = 0.f;

    // ---------------- Phase A: stats ----------------
    for (int nt = 0; nt < 64; nt++) {
        #pragma unroll
        for (int s2 = 0; s2 < 2; s2++) {
            int row = s2 * 16 + (t >> 4), c4 = (t & 15) * 4;
            float4 v = *(const float4*)&Kg[(size_t)(nt * 32 + row) * 64 + c4];
            Ks[row * KSTR + c4 + 0] = __uint_as_float(f2tf(v.x));
            Ks[row * KSTR + c4 + 1] = __uint_as_float(f2tf(v.y));
            Ks[row * KSTR + c4 + 2] = __uint_as_float(f2tf(v.z));
            Ks[row * KSTR + c4 + 3] = __uint_as_float(f2tf(v.w));
        }
        __syncthreads();

        float acc[4][4];
        #pragma unroll
        for (int j = 0; j < 4; j++)
            #pragma unroll
            for (int i = 0; i < 4; i++) acc[j][i] = 0.f;
        #pragma unroll
        for (int ks = 0; ks < 8; ks++)
            #pragma unroll
            for (int j = 0; j < 4; j++) {
                uint32_t b0 = __float_as_uint(Ks[(8 * j + g) * KSTR + 8 * ks + tg]);
                uint32_t b1 = __float_as_uint(Ks[(8 * j + g) * KSTR + 8 * ks + tg + 4]);
                mma8(acc[j], a[ks], b0, b1);
            }

        float mx0 = BIG_NEG, mx1 = BIG_NEG;
        #pragma unroll
        for (int j = 0; j < 4; j++) {
            int kc = nt * 32 + 8 * j + 2 * tg;
            int2   mk0 = *(const int2*)  &mask[((size_t)b_ * SEQ + rowA)     * SEQ + kc];
            int2   mk1 = *(const int2*)  &mask[((size_t)b_ * SEQ + rowA + 8) * SEQ + kc];
            float2 gr0 = *(const float2*)&grm[(size_t)rowA       * SEQ + kc];
            float2 gr1 = *(const float2*)&grm[(size_t)(rowA + 8) * SEQ + kc];
            acc[j][0] = mk0.x ? acc[j][0] * 0.125f + gr0.x : BIG_NEG;
            acc[j][1] = mk0.y ? acc[j][1] * 0.125f + gr0.y : BIG_NEG;
            acc[j][2] = mk1.x ? acc[j][2] * 0.125f + gr1.x : BIG_NEG;
            acc[j][3] = mk1.y ? acc[j][3] * 0.125f + gr1.y : BIG_NEG;
            mx0 = fmaxf(mx0, fmaxf(acc[j][0], acc[j][1]));
            mx1 = fmaxf(mx1, fmaxf(acc[j][2], acc[j][3]));
        }
        mx0 = fmaxf(mx0, __shfl_xor_sync(0xffffffffu, mx0, 1));
        mx0 = fmaxf(mx0, __shfl_xor_sync(0xffffffffu, mx0, 2));
        mx1 = fmaxf(mx1, __shfl_xor_sync(0xffffffffu, mx1, 1));
        mx1 = fmaxf(mx1, __shfl_xor_sync(0xffffffffu, mx1, 2));
        float mn0 = fmaxf(m0r, mx0), mn1 = fmaxf(m1r, mx1);
        float su0 = 0.f, su1 = 0.f;
        #pragma unroll
        for (int j = 0; j < 4; j++) {
            su0 += (acc[j][0] > -1e29f) ? __expf(acc[j][0] - mn0) : 0.f;
            su0 += (acc[j][1] > -1e29f) ? __expf(acc[j][1] - mn0) : 0.f;
            su1 += (acc[j][2] > -1e29f) ? __expf(acc[j][2] - mn1) : 0.f;
            su1 += (acc[j][3] > -1e29f) ? __expf(acc[j][3] - mn1) : 0.f;
        }
        su0 += __shfl_xor_sync(0xffffffffu, su0, 1);
        su0 += __shfl_xor_sync(0xffffffffu, su0, 2);
        su1 += __shfl_xor_sync(0xffffffffu, su1, 1);
        su1 += __shfl_xor_sync(0xffffffffu, su1, 2);
        l0r = (mn0 > -1e29f) ? l0r * __expf(m0r - mn0) + su0 : 0.f;
        l1r = (mn1 > -1e29f) ? l1r * __expf(m1r - mn1) + su1 : 0.f;
        m0r = mn0;  m1r = mn1;
        __syncthreads();
    }

    const float il0 = 1.0f / l0r, il1 = 1.0f / l1r;

    // ---------------- Phase B: P write + O = P @ V ----------------
    float acc_o[8][4];
    #pragma unroll
    for (int j = 0; j < 8; j++)
        #pragma unroll
        for (int i = 0; i < 4; i++) acc_o[j][i] = 0.f;

    for (int nt = 0; nt < 64; nt++) {
        #pragma unroll
        for (int s2 = 0; s2 < 2; s2++) {
            int row = s2 * 16 + (t >> 4), c4 = (t & 15) * 4;
            float4 kv = *(const float4*)&Kg[(size_t)(nt * 32 + row) * 64 + c4];
            Ks[row * KSTR + c4 + 0] = __uint_as_float(f2tf(kv.x));
            Ks[row * KSTR + c4 + 1] = __uint_as_float(f2tf(kv.y));
            Ks[row * KSTR + c4 + 2] = __uint_as_float(f2tf(kv.z));
            Ks[row * KSTR + c4 + 3] = __uint_as_float(f2tf(kv.w));
            float4 vv = *(const float4*)&V[(size_t)(nt * 32 + row) * 64 + c4];
            Vs[row * VSTR + c4 + 0] = __uint_as_float(f2tf(vv.x));
            Vs[row * VSTR + c4 + 1] = __uint_as_float(f2tf(vv.y));
            Vs[row * VSTR + c4 + 2] = __uint_as_float(f2tf(vv.z));
            Vs[row * VSTR + c4 + 3] = __uint_as_float(f2tf(vv.w));
        }
        __syncthreads();

        // Recompute S tile
        float accs[4][4];
        #pragma unroll
        for (int j = 0; j < 4; j++)
            #pragma unroll
            for (int i = 0; i < 4; i++) accs[j][i] = 0.f;
        #pragma unroll
        for (int ks = 0; ks < 8; ks++)
            #pragma unroll
            for (int j = 0; j < 4; j++) {
                uint32_t b0 = __float_as_uint(Ks[(8 * j + g) * KSTR + 8 * ks + tg]);
                uint32_t b1 = __float_as_uint(Ks[(8 * j + g) * KSTR + 8 * ks + tg + 4]);
                mma8(accs[j], a[ks], b0, b1);
            }

        // p = exp(s - m) / l; write P; stage tf32(p) for PV mma
        #pragma unroll
        for (int j = 0; j < 4; j++) {
            int kc = nt * 32 + 8 * j + 2 * tg;
            int2   mk0 = *(const int2*)  &mask[((size_t)b_ * SEQ + rowA)     * SEQ + kc];
            int2   mk1 = *(const int2*)  &mask[((size_t)b_ * SEQ + rowA + 8) * SEQ + kc];
            float2 gr0 = *(const float2*)&grm[(size_t)rowA       * SEQ + kc];
            float2 gr1 = *(const float2*)&grm[(size_t)(rowA + 8) * SEQ + kc];
            float p00 = mk0.x ? __expf(accs[j][0] * 0.125f + gr0.x - m0r) * il0 : 0.f;
            float p01 = mk0.y ? __expf(accs[j][1] * 0.125f + gr0.y - m0r) * il0 : 0.f;
            float p10 = mk1.x ? __expf(accs[j][2] * 0.125f + gr1.x - m1r) * il1 : 0.f;
            float p11 = mk1.y ? __expf(accs[j][3] * 0.125f + gr1.y - m1r) * il1 : 0.f;
            *(float2*)&outP[(size_t)rowA       * SEQ + kc] = make_float2(p00, p01);
            *(float2*)&outP[(size_t)(rowA + 8) * SEQ + kc] = make_float2(p10, p11);
            int c = 8 * j + 2 * tg;
            Ps[rql * PSTR + c]           = __uint_as_float(f2tf(p00));
            Ps[rql * PSTR + c + 1]       = __uint_as_float(f2tf(p01));
            Ps[(rql + 8) * PSTR + c]     = __uint_as_float(f2tf(p10));
            Ps[(rql + 8) * PSTR + c + 1] = __uint_as_float(f2tf(p11));
        }
        __syncwarp();   // Ps rows of this warp written by its own lanes only

        // O += P_tile @ V_tile  (16q x 64d per warp, k=32)
        #pragma unroll
        for (int ks = 0; ks < 4; ks++) {
            uint32_t af[4];
            af[0] = __float_as_uint(Ps[rql * PSTR + 8 * ks + tg]);
            af[1] = __float_as_uint(Ps[(rql + 8) * PSTR + 8 * ks + tg]);
            af[2] = __float_as_uint(Ps[rql * PSTR + 8 * ks + tg + 4]);
            af[3] = __float_as_uint(Ps[(rql + 8) * PSTR + 8 * ks + tg + 4]);
            #pragma unroll
            for (int j = 0; j < 8; j++) {
                uint32_t b0 = __float_as_uint(Vs[(8 * ks + tg)     * VSTR + 8 * j + g]);
                uint32_t b1 = __float_as_uint(Vs[(8 * ks + tg + 4) * VSTR + 8 * j + g]);
                mma8(acc_o[j], af, b0, b1);
            }
        }
        __syncthreads();
    }

    // Epilogue: O -> g_o[b][l][h*64 + d]
    #pragma unroll
    for (int j = 0; j < 8; j++) {
        int d = h * 64 + 8 * j + 2 * tg;
        *(float2*)&g_o[((size_t)b_ * SEQ + rowA)     * EMB + d] =
            make_float2(acc_o[j][0], acc_o[j][1]);
        *(float2*)&g_o[((size_t)b_ * SEQ + rowA + 8) * EMB + d] =
            make_float2(acc_o[j][2], acc_o[j][3]);
    }
}

// ---------------------------------------------------------------------------
extern "C" void kernel_launch(void* const* d_in, const int* in_sizes, int n_in,
                              void* d_out, int out_size)
{
    const float* query = (const float*)d_in[0];
    const float* key_  = (const float*)d_in[1];
    const float* value = (const float*)d_in[2];
    const int*   mask  = (const int*)  d_in[3];
    const float* grm   = (const float*)d_in[4];
    const float* Wq = (const float*)d_in[5];
    const float* bq = (const float*)d_in[6];
    const float* Wk = (const float*)d_in[7];
    const float* bk = (const float*)d_in[8];
    const float* Wv = (const float*)d_in[9];
    const float* bv = (const float*)d_in[10];
    const float* Wo = (const float*)d_in[11];
    const float* bo = (const float*)d_in[12];

    float* out  = (float*)d_out;                       // [B, L, E]
    float* attn = out + (size_t)BATCH * SEQ * EMB;     // [B, H, L, L]

    float *q_, *k_, *v_, *o_;
    cudaGetSymbolAddress((void**)&q_, g_q);
    cudaGetSymbolAddress((void**)&k_, g_k);
    cudaGetSymbolAddress((void**)&v_, g_v);
    cudaGetSymbolAddress((void**)&o_, g_o);

    dim3 gProj(EMB / 64, MTOT / 128);        // (8, 64)
    proj_tf32_kernel<<<gProj, 256>>>(query, Wq, bq, q_, 1);
    proj_tf32_kernel<<<gProj, 256>>>(key_,  Wk, bk, k_, 1);
    proj_tf32_kernel<<<gProj, 256>>>(value, Wv, bv, v_, 1);

    dim3 gF(SEQ / 128, BH);                  // (16, 32)
    flash_kernel<<<gF, 256>>>(mask, grm, attn);

    proj_tf32_kernel<<<gProj, 256>>>(o_, Wo, bo, out, 0);
}